// round 13
// baseline (speedup 1.0000x reference)
#include <cuda_runtime.h>
#include <math.h>

#define RT 4
#define N_AMB 1023
#define SLOPE 0.2f
#define NPB 8
#define NODE_BLKS 128
#define GRID 129
#define NT 512

__device__ float d_gr0[256];
__device__ float d_e0g[4];
__device__ float d_c0g[64];
__device__ float d_pz[GRID * 4];
__device__ float d_pacc[GRID * 256];
__device__ int   d_flag1, d_go, d_cnt1, d_cnt2;

__device__ __forceinline__ float leaky(float x) { return x >= 0.f ? x : SLOPE * x; }
__device__ __forceinline__ float red8(float v) {
    v += __shfl_xor_sync(0xffffffffu, v, 1);
    v += __shfl_xor_sync(0xffffffffu, v, 2);
    v += __shfl_xor_sync(0xffffffffu, v, 4);
    return v;
}
__device__ __forceinline__ float warpsum(float v) {
    #pragma unroll
    for (int off = 16; off; off >>= 1) v += __shfl_xor_sync(0xffffffffu, v, off);
    return v;
}
__device__ __forceinline__ float dot8(const float* __restrict__ w, const float* __restrict__ x) {
    const float4* w4 = (const float4*)w;
    float4 a = w4[0], b = w4[1];
    return a.x*x[0] + a.y*x[1] + a.z*x[2] + a.w*x[3]
         + b.x*x[4] + b.y*x[5] + b.z*x[6] + b.w*x[7];
}
__device__ __forceinline__ float dot16(const float* __restrict__ w, const float* __restrict__ x) {
    const float4* w4 = (const float4*)w;
    float4 a = w4[0], b = w4[1], c = w4[2], d = w4[3];
    return a.x*x[0] + a.y*x[1] + a.z*x[2] + a.w*x[3]
         + b.x*x[4] + b.y*x[5] + b.z*x[6] + b.w*x[7]
         + c.x*x[8] + c.y*x[9] + c.z*x[10] + c.w*x[11]
         + d.x*x[12] + d.y*x[13] + d.z*x[14] + d.w*x[15];
}
__device__ __forceinline__ float d44(float4 w, float4 x) {
    return w.x*x.x + w.y*x.y + w.z*x.z + w.w*x.w;
}
__device__ __forceinline__ void unpack2(unsigned long long v, float& x, float& y) {
    asm("mov.b64 {%0, %1}, %2;" : "=f"(x), "=f"(y) : "l"(v));
}
__device__ __forceinline__ void fma2(unsigned long long& d, unsigned long long a, unsigned long long b) {
    asm("fma.rn.f32x2 %0, %1, %2, %0;" : "+l"(d) : "l"(a), "l"(b));
}
__device__ __forceinline__ float collapse(unsigned long long v) {
    float x, y; unpack2(v, x, y); return x + y;
}

__global__ void __launch_bounds__(NT, 1)
mega(const float* __restrict__ hidden, const float* __restrict__ amb,
     const float* __restrict__ ta,
     const float* __restrict__ Wself,  const float* __restrict__ bself,
     const float* __restrict__ Wmerge, const float* __restrict__ bmerge,
     const float* __restrict__ Wtrans, const float* __restrict__ btrans,
     const float* __restrict__ Wl,     const float* __restrict__ Wr,
     const float* __restrict__ wattn,
     const float* __restrict__ Wd0,    const float* __restrict__ bd0,
     const float* __restrict__ Wd1,    const float* __restrict__ bd1,
     const float* __restrict__ Wd2,    const float* __restrict__ bd2,
     float* __restrict__ out) {
    // pool: node: s_v[0..2304) s_p1[2304..2816) s_y0[2816..3328) s_y1[3328..4352)
    //       routing: Wmerge cache [0..8192); combiner: s_part [0..512)
    __shared__ __align__(16) float pool[8192];
    __shared__ __align__(16) float s_hk[640];   // h k-pair-packed [kp][r*2+par], pad20; routing: rtmp|bufA|bufB
    __shared__ __align__(16) float s_h[512];    // h row-major; routing: rin|ravg then gl|gr
    __shared__ float s_eall[32], s_wv[32];
    __shared__ float s_Zi[4], s_h2[64], s_c0[64], s_e0[8], s_e0s[4];

    float* const s_v  = pool;            // 256 cols x pad9
    float* const s_p1 = pool + 2304;
    float* const s_y0 = pool + 2816;
    float* const s_y1 = pool + 3328;

    const int tid = threadIdx.x, lane = tid & 31, warp = tid >> 5;
    const int oid = tid >> 3, q8 = tid & 7;
    const int blk = blockIdx.x;
    const int base = blk * NPB;
    const int kb = q8 * 8;

    // ================= block 128: routing + node 0 + COMBINER =================
    if (blk == NODE_BLKS) {
        float* rin  = s_h;            // 64
        float* ravg = s_h + 64;       // 256
        float* rtmp = s_hk;           // 256
        float* bufA = s_hk + 256;     // 128
        float* bufB = s_hk + 384;     // 128
        if (tid >= 256) {             // prefetch Wmerge 32KB into pool
            int t = tid - 256;
            float4* dst = (float4*)pool;
            const float4* src = (const float4*)Wmerge;
            #pragma unroll
            for (int i = 0; i < 8; i++) dst[t + i * 256] = src[t + i * 256];
        } else {
            if (tid < 64) rin[tid] = hidden[tid];
            int rt = tid >> 6, oo = tid & 63;
            ravg[tid] = (ta[(rt * 3 + 0) * 64 + oo] + ta[(rt * 3 + 1) * 64 + oo] +
                         ta[(rt * 3 + 2) * 64 + oo]) * (1.f / 3.f);
        }
        __syncthreads();
        if (tid < 256) {
            int o4 = tid >> 2, q4 = tid & 3;
            float s = dot16(Wself + o4 * 64 + q4 * 16, &rin[q4 * 16]);
            s += __shfl_xor_sync(0xffffffffu, s, 1);
            s += __shfl_xor_sync(0xffffffffu, s, 2);
            if (q4 == 0) bufA[o4] = bself[o4] + s;
            int rt = tid >> 6, oo = tid & 63;
            const float* av = &ravg[rt * 64];
            float t = btrans[rt * 64 + oo];
            t += dot16(Wtrans + rt * 4096 + oo * 64,      av);
            t += dot16(Wtrans + rt * 4096 + oo * 64 + 16, av + 16);
            t += dot16(Wtrans + rt * 4096 + oo * 64 + 32, av + 32);
            t += dot16(Wtrans + rt * 4096 + oo * 64 + 48, av + 48);
            rtmp[tid] = t;
        }
        __syncthreads();
        if (tid < 64) bufA[64 + tid] = rtmp[tid];
        __syncthreads();
        {   // double-buffered merge chain: 1 sync per iteration
            float bm = bmerge[oid];
            float* bufs[2] = { bufA, bufB };
            #pragma unroll
            for (int rt = 0; rt < RT; rt++) {
                float* cur = bufs[rt & 1];
                float* nxt = bufs[(rt + 1) & 1];
                float m = dot16(&pool[oid * 128 + q8 * 16], &cur[q8 * 16]);
                m = red8(m);
                if (q8 == 0) nxt[oid] = leaky(bm + m);
                if (tid < 64 && rt < 3) nxt[64 + tid] = rtmp[(rt + 1) * 64 + tid];
                __syncthreads();
            }
        }
        float* rcat = ((RT & 1) ? bufB : bufA);
        {   // gl0 -> s_h[0..255], gr0 -> s_h[256..511] + d_gr0
            int o = tid >> 1, q2 = tid & 1;
            float gl = dot16(Wl + o * 64 + q2 * 32,      &rcat[q2 * 32])
                     + dot16(Wl + o * 64 + q2 * 32 + 16, &rcat[q2 * 32 + 16]);
            float gr = dot16(Wr + o * 64 + q2 * 32,      &rcat[q2 * 32])
                     + dot16(Wr + o * 64 + q2 * 32 + 16, &rcat[q2 * 32 + 16]);
            gl += __shfl_xor_sync(0xffffffffu, gl, 1);
            gr += __shfl_xor_sync(0xffffffffu, gr, 1);
            if (q2 == 0) { s_h[o] = gl; s_h[256 + o] = gr; d_gr0[o] = gr; }
        }
        __syncthreads();
        if (warp < 8) {                   // node-0 logits e0[h] (the exp reference)
            int h = warp >> 1, half = warp & 1, f = half * 32 + lane;
            float c = leaky(s_h[h * 64 + f] + s_h[256 + h * 64 + f]) * wattn[f];
            c = warpsum(c);
            if (lane == 0) s_e0[h * 2 + half] = c;
        }
        __syncthreads();
        if (tid < 4) {
            d_e0g[tid] = s_e0[tid * 2] + s_e0[tid * 2 + 1];
            d_pz[NODE_BLKS * 4 + tid] = 1.f;       // exp(e0-e0) summed = 1
        }
        if (tid < 256) d_pacc[NODE_BLKS * 256 + tid] = s_h[256 + tid];
        __threadfence();
        __syncthreads();
        if (tid == 0) *(volatile int*)&d_flag1 = 1;   // release gr0 + e0
        // ---- wait for all node partials, then combine ONCE (no max phase) ----
        if (tid == 0) {
            volatile int* c = &d_cnt1;
            while (*c < NODE_BLKS) __nanosleep(64);
            __threadfence();
        }
        __syncthreads();
        {
            float* s_part = pool;
            int o = tid & 255, half = tid >> 8, b0 = half ? 65 : 0, b1 = half ? GRID : 65;
            float a = 0.f;
            #pragma unroll 16
            for (int b = b0; b < b1; b++) a += d_pacc[b * 256 + o];
            s_part[half * 256 + o] = a;
            if (warp < 4) {               // pz sums per head
                float z = d_pz[lane * 4 + warp] + d_pz[(lane + 32) * 4 + warp]
                        + d_pz[(lane + 64) * 4 + warp] + d_pz[(lane + 96) * 4 + warp];
                if (lane == 0) z += d_pz[NODE_BLKS * 4 + warp];
                z = warpsum(z);
                if (lane == 0) s_Zi[warp] = 1.f / z;
            }
            __syncthreads();
            if (tid < 64) {
                float h2 = 0.f;
                #pragma unroll
                for (int hh = 0; hh < 4; hh++)
                    h2 += (s_part[hh * 64 + tid] + s_part[256 + hh * 64 + tid]) * s_Zi[hh];
                s_h2[tid] = 0.25f * h2;
            }
            __syncthreads();
            {   // c0 -> global broadcast
                float p = dot8(Wd0 + oid * 128 + 64 + kb, &s_h2[kb]);
                p = red8(p);
                if (q8 == 0) d_c0g[oid] = bd0[oid] + p;
            }
        }
        __threadfence();
        __syncthreads();
        if (tid == 0) {
            *(volatile int*)&d_go = 1;
            if (atomicAdd(&d_cnt2, 1) == GRID - 1) {
                d_cnt1 = 0; d_go = 0; d_flag1 = 0;
                __threadfence();
                *(volatile int*)&d_cnt2 = 0;
            }
        }
        return;
    }

    // ===================== node blocks 0..127 =====================
    {   // h rows (clamped pad): row-major AND k-pair packed [kp*20 + r*2 + parity]
        int r = tid >> 6, k = tid & 63;
        int ar_ = base + r; if (ar_ >= N_AMB) ar_ = N_AMB - 1;
        float hv = amb[ar_ * 64 + k];
        s_h[r * 64 + k] = hv;
        s_hk[(k >> 1) * 20 + r * 2 + (k & 1)] = hv;
    }
    __syncthreads();

    // -------- pass A: col-per-thread, k-pair packed f32x2, zero repack movs --
    const int col = tid & 255;
    const int mat = tid >> 8;            // 0 = Wl (-> logits), 1 = Wr (-> pacc)
    const float* Wmat = mat ? Wr : Wl;
    float rowv[8];
    {
        unsigned long long acc[8];
        #pragma unroll
        for (int r = 0; r < 8; r++) acc[r] = 0ull;
        #pragma unroll
        for (int t = 0; t < 4; t++) {
            // weights as ready-made {w_2k, w_2k+1} pairs
            ulonglong2 wv0 = *(const ulonglong2*)(Wmat + col * 64 + t * 16);
            ulonglong2 wv1 = *(const ulonglong2*)(Wmat + col * 64 + t * 16 + 4);
            ulonglong2 wv2 = *(const ulonglong2*)(Wmat + col * 64 + t * 16 + 8);
            ulonglong2 wv3 = *(const ulonglong2*)(Wmat + col * 64 + t * 16 + 12);
            unsigned long long wp[8] = { wv0.x, wv0.y, wv1.x, wv1.y,
                                         wv2.x, wv2.y, wv3.x, wv3.y };
            #pragma unroll
            for (int j = 0; j < 8; j++) {
                int kp = t * 8 + j;
                const float* hb = &s_hk[kp * 20];
                ulonglong2 hA = *(const ulonglong2*)(hb);
                ulonglong2 hB = *(const ulonglong2*)(hb + 4);
                ulonglong2 hC = *(const ulonglong2*)(hb + 8);
                ulonglong2 hD = *(const ulonglong2*)(hb + 12);
                fma2(acc[0], wp[j], hA.x); fma2(acc[1], wp[j], hA.y);
                fma2(acc[2], wp[j], hB.x); fma2(acc[3], wp[j], hB.y);
                fma2(acc[4], wp[j], hC.x); fma2(acc[5], wp[j], hC.y);
                fma2(acc[6], wp[j], hD.x); fma2(acc[7], wp[j], hD.y);
            }
        }
        #pragma unroll
        for (int r = 0; r < 8; r++) rowv[r] = collapse(acc[r]);
    }
    // MLP stage-1 dots pre-barrier (overlaps cold Wd0 + flag wait)
    {
        const float4* w4 = (const float4*)(Wd0 + oid * 128 + kb);
        float4 a = w4[0], b = w4[1];
        #pragma unroll
        for (int r = 0; r < NPB; r++) {
            float4 xa = *(const float4*)&s_h[r * 64 + kb];
            float4 xb = *(const float4*)&s_h[r * 64 + kb + 4];
            float s = d44(a, xa) + d44(b, xb);
            s = red8(s);
            if (q8 == 0) s_p1[r * 64 + oid] = s;
        }
    }
    // prefetch MLP stage-2/3 weights into regs
    float4 w2a0, w2a1, w2b0, w2b1, w3a, w3b;
    float bb0, bb1, b3;
    const int r3 = tid >> 6, sub3 = tid & 63, o3 = sub3 >> 4, q16 = sub3 & 15;
    {
        const float4* w4 = (const float4*)(Wd1 + oid * 64 + kb);
        w2a0 = w4[0]; w2a1 = w4[1];
        const float4* w5 = (const float4*)(Wd1 + (64 + oid) * 64 + kb);
        w2b0 = w5[0]; w2b1 = w5[1];
        bb0 = bd1[oid]; bb1 = bd1[64 + oid];
        const float4* w6 = (const float4*)(Wd2 + o3 * 128 + q16 * 8);
        w3a = w6[0]; w3b = w6[1];
        b3 = bd2[o3];
    }
    if (tid == 0) {
        volatile int* f = &d_flag1;
        while (!*f) __nanosleep(32);
        __threadfence();
    }
    __syncthreads();
    if (tid < 4) s_e0s[tid] = d_e0g[tid];   // e0 reference -> smem

    // -------- pass B: logits from registers --------
    if (mat == 0) {
        float g0 = d_gr0[col];
        float wa = wattn[col & 63];
        #pragma unroll
        for (int r = 0; r < NPB; r++)
            s_v[col * 9 + r] = leaky(rowv[r] + g0) * wa;
    }
    __syncthreads();
    {   // reduce v over 64 cols per (head,row): 16 threads each
        int hr = tid >> 4, sub = tid & 15;
        int h = hr >> 3, r = hr & 7;
        int cb = h * 64 + sub * 4;
        float s = s_v[cb * 9 + r] + s_v[(cb + 1) * 9 + r]
                + s_v[(cb + 2) * 9 + r] + s_v[(cb + 3) * 9 + r];
        s += __shfl_xor_sync(0xffffffffu, s, 1);
        s += __shfl_xor_sync(0xffffffffu, s, 2);
        s += __shfl_xor_sync(0xffffffffu, s, 4);
        s += __shfl_xor_sync(0xffffffffu, s, 8);
        if (sub == 0) s_eall[h * 8 + r] = s;
    }
    __syncthreads();
    if (tid < 32) {                     // w = exp(e - e0); pz via 8-lane shfl
        int h = tid >> 3, r = tid & 7;
        float w = (base + r < N_AMB) ? __expf(s_eall[tid] - s_e0s[h]) : 0.f;
        s_wv[tid] = w;
        float z = w;
        z += __shfl_xor_sync(0xffffffffu, z, 1);
        z += __shfl_xor_sync(0xffffffffu, z, 2);
        z += __shfl_xor_sync(0xffffffffu, z, 4);
        if (r == 0) d_pz[blk * 4 + h] = z;
    }
    __syncthreads();
    if (mat == 1) {                      // pacc straight from rowv registers
        int h = col >> 6;
        float accf = 0.f;
        #pragma unroll
        for (int r = 0; r < NPB; r++)
            accf = fmaf(s_wv[h * 8 + r], rowv[r], accf);
        d_pacc[blk * 256 + col] = accf;
    }
    __threadfence();
    __syncthreads();
    if (tid == 0) {
        atomicAdd(&d_cnt1, 1);
        volatile int* g = &d_go;         // combiner releases
        while (!*g) __nanosleep(64);
        __threadfence();
    }
    __syncthreads();

    // read broadcast c0
    if (tid < 64) s_c0[tid] = d_c0g[tid];
    __syncthreads();

    // -------- MLP finish --------
    s_y0[tid] = leaky(s_c0[tid & 63] + s_p1[tid]);   // stage 1 elementwise
    __syncthreads();
    #pragma unroll
    for (int r = 0; r < NPB; r++) {      // stage 2
        float4 xa = *(const float4*)&s_y0[r * 64 + kb];
        float4 xb = *(const float4*)&s_y0[r * 64 + kb + 4];
        float s0 = d44(w2a0, xa) + d44(w2a1, xb);
        float s1 = d44(w2b0, xa) + d44(w2b1, xb);
        s0 = red8(s0);
        s1 = red8(s1);
        if (q8 == 0) {
            s_y1[r * 128 + oid]      = leaky(bb0 + s0);
            s_y1[r * 128 + 64 + oid] = leaky(bb1 + s1);
        }
    }
    __syncthreads();
    {                                    // stage 3 + sigmoid
        float4 ya = *(const float4*)&s_y1[r3 * 128 + q16 * 8];
        float4 yb = *(const float4*)&s_y1[r3 * 128 + q16 * 8 + 4];
        float p = d44(w3a, ya) + d44(w3b, yb);
        p += __shfl_xor_sync(0xffffffffu, p, 1);
        p += __shfl_xor_sync(0xffffffffu, p, 2);
        p += __shfl_xor_sync(0xffffffffu, p, 4);
        p += __shfl_xor_sync(0xffffffffu, p, 8);
        int arr = base + r3;
        if (q16 == 0 && arr < N_AMB)
            out[arr * 4 + o3] = 1.f / (1.f + __expf(-(b3 + p)));
    }

    if (tid == 0) {
        if (atomicAdd(&d_cnt2, 1) == GRID - 1) {
            d_cnt1 = 0; d_go = 0; d_flag1 = 0;
            __threadfence();
            *(volatile int*)&d_cnt2 = 0;
        }
    }
}

extern "C" void kernel_launch(void* const* d_in, const int* in_sizes, int n_in,
                              void* d_out, int out_size) {
    const float* hidden = (const float*)d_in[0];
    const float* amb    = (const float*)d_in[1];
    const float* ta     = (const float*)d_in[2];
    const float* Wself  = (const float*)d_in[3];
    const float* bself  = (const float*)d_in[4];
    const float* Wmerge = (const float*)d_in[5];
    const float* bmerge = (const float*)d_in[6];
    const float* Wtrans = (const float*)d_in[7];
    const float* btrans = (const float*)d_in[8];
    const float* Wl     = (const float*)d_in[9];
    const float* Wr     = (const float*)d_in[10];
    const float* wattn  = (const float*)d_in[11];
    const float* Wd0    = (const float*)d_in[12];
    const float* bd0    = (const float*)d_in[13];
    const float* Wd1    = (const float*)d_in[14];
    const float* bd1    = (const float*)d_in[15];
    const float* Wd2    = (const float*)d_in[16];
    const float* bd2    = (const float*)d_in[17];
    float* out = (float*)d_out;

    mega<<<GRID, NT>>>(hidden, amb, ta, Wself, bself, Wmerge, bmerge,
                       Wtrans, btrans, Wl, Wr, wattn,
                       Wd0, bd0, Wd1, bd1, Wd2, bd2, out);
}

// round 14
// speedup vs baseline: 1.0483x; 1.0483x over previous
#include <cuda_runtime.h>
#include <math.h>

#define RT 4
#define N_AMB 1023
#define SLOPE 0.2f
#define NPB 8
#define NODE_BLKS 128
#define GRID 129
#define NT 512

__device__ float d_gr0[256];
__device__ float d_e0g[4];
__device__ float d_c0g[64];
__device__ float d_paccsum[256];   // atomic-accumulated; zeroed by last block each launch
__device__ float d_zsum[4];        // atomic-accumulated; zeroed by last block each launch
__device__ int   d_flag1, d_go, d_cnt1, d_cnt2;

__device__ __forceinline__ float leaky(float x) { return x >= 0.f ? x : SLOPE * x; }
__device__ __forceinline__ float red8(float v) {
    v += __shfl_xor_sync(0xffffffffu, v, 1);
    v += __shfl_xor_sync(0xffffffffu, v, 2);
    v += __shfl_xor_sync(0xffffffffu, v, 4);
    return v;
}
__device__ __forceinline__ float warpsum(float v) {
    #pragma unroll
    for (int off = 16; off; off >>= 1) v += __shfl_xor_sync(0xffffffffu, v, off);
    return v;
}
__device__ __forceinline__ float dot16(const float* __restrict__ w, const float* __restrict__ x) {
    const float4* w4 = (const float4*)w;
    float4 a = w4[0], b = w4[1], c = w4[2], d = w4[3];
    return a.x*x[0] + a.y*x[1] + a.z*x[2] + a.w*x[3]
         + b.x*x[4] + b.y*x[5] + b.z*x[6] + b.w*x[7]
         + c.x*x[8] + c.y*x[9] + c.z*x[10] + c.w*x[11]
         + d.x*x[12] + d.y*x[13] + d.z*x[14] + d.w*x[15];
}
__device__ __forceinline__ float d44(float4 w, float4 x) {
    return w.x*x.x + w.y*x.y + w.z*x.z + w.w*x.w;
}
__device__ __forceinline__ void unpack2(unsigned long long v, float& x, float& y) {
    asm("mov.b64 {%0, %1}, %2;" : "=f"(x), "=f"(y) : "l"(v));
}
__device__ __forceinline__ void fma2(unsigned long long& d, unsigned long long a, unsigned long long b) {
    asm("fma.rn.f32x2 %0, %1, %2, %0;" : "+l"(d) : "l"(a), "l"(b));
}
__device__ __forceinline__ float collapse(unsigned long long v) {
    float x, y; unpack2(v, x, y); return x + y;
}

__global__ void __launch_bounds__(NT, 1)
mega(const float* __restrict__ hidden, const float* __restrict__ amb,
     const float* __restrict__ ta,
     const float* __restrict__ Wself,  const float* __restrict__ bself,
     const float* __restrict__ Wmerge, const float* __restrict__ bmerge,
     const float* __restrict__ Wtrans, const float* __restrict__ btrans,
     const float* __restrict__ Wl,     const float* __restrict__ Wr,
     const float* __restrict__ wattn,
     const float* __restrict__ Wd0,    const float* __restrict__ bd0,
     const float* __restrict__ Wd1,    const float* __restrict__ bd1,
     const float* __restrict__ Wd2,    const float* __restrict__ bd2,
     float* __restrict__ out) {
    __shared__ __align__(16) float pool[8192];
    __shared__ __align__(16) float s_hk[640];   // h k-pair-packed; routing: rtmp|bufA|bufB
    __shared__ __align__(16) float s_h[512];    // h row-major; routing: rin|ravg then gl|gr
    __shared__ float s_eall[32], s_wv[32];
    __shared__ float s_Zi[4], s_h2[64], s_c0[64], s_e0[8], s_e0s[4];
    __shared__ int s_last;

    float* const s_v  = pool;            // 256 cols x pad9
    float* const s_p1 = pool + 2304;
    float* const s_y0 = pool + 2816;
    float* const s_y1 = pool + 3328;

    const int tid = threadIdx.x, lane = tid & 31, warp = tid >> 5;
    const int oid = tid >> 3, q8 = tid & 7;
    const int blk = blockIdx.x;
    const int base = blk * NPB;
    const int kb = q8 * 8;

    // ================= block 128: routing + node 0 + COMBINER =================
    if (blk == NODE_BLKS) {
        // prefetch c0 weights NOW (cold DRAM; needed only at combine tail)
        float4 wc0a = *(const float4*)(Wd0 + oid * 128 + 64 + kb);
        float4 wc0b = *(const float4*)(Wd0 + oid * 128 + 64 + kb + 4);
        float bd0v = bd0[oid];

        float* rin  = s_h;            // 64
        float* ravg = s_h + 64;       // 256
        float* rtmp = s_hk;           // 256
        float* bufA = s_hk + 256;     // 128
        float* bufB = s_hk + 384;     // 128
        if (tid >= 256) {             // prefetch Wmerge 32KB into pool
            int t = tid - 256;
            float4* dst = (float4*)pool;
            const float4* src = (const float4*)Wmerge;
            #pragma unroll
            for (int i = 0; i < 8; i++) dst[t + i * 256] = src[t + i * 256];
        } else {
            if (tid < 64) rin[tid] = hidden[tid];
            int rt = tid >> 6, oo = tid & 63;
            ravg[tid] = (ta[(rt * 3 + 0) * 64 + oo] + ta[(rt * 3 + 1) * 64 + oo] +
                         ta[(rt * 3 + 2) * 64 + oo]) * (1.f / 3.f);
        }
        __syncthreads();
        if (tid < 256) {
            int o4 = tid >> 2, q4 = tid & 3;
            float s = dot16(Wself + o4 * 64 + q4 * 16, &rin[q4 * 16]);
            s += __shfl_xor_sync(0xffffffffu, s, 1);
            s += __shfl_xor_sync(0xffffffffu, s, 2);
            if (q4 == 0) bufA[o4] = bself[o4] + s;
            int rt = tid >> 6, oo = tid & 63;
            const float* av = &ravg[rt * 64];
            float t = btrans[rt * 64 + oo];
            t += dot16(Wtrans + rt * 4096 + oo * 64,      av);
            t += dot16(Wtrans + rt * 4096 + oo * 64 + 16, av + 16);
            t += dot16(Wtrans + rt * 4096 + oo * 64 + 32, av + 32);
            t += dot16(Wtrans + rt * 4096 + oo * 64 + 48, av + 48);
            rtmp[tid] = t;
        }
        __syncthreads();
        if (tid < 64) bufA[64 + tid] = rtmp[tid];
        __syncthreads();
        {   // double-buffered merge chain: 1 sync per iteration
            float bm = bmerge[oid];
            float* bufs[2] = { bufA, bufB };
            #pragma unroll
            for (int rt = 0; rt < RT; rt++) {
                float* cur = bufs[rt & 1];
                float* nxt = bufs[(rt + 1) & 1];
                float m = dot16(&pool[oid * 128 + q8 * 16], &cur[q8 * 16]);
                m = red8(m);
                if (q8 == 0) nxt[oid] = leaky(bm + m);
                if (tid < 64 && rt < 3) nxt[64 + tid] = rtmp[(rt + 1) * 64 + tid];
                __syncthreads();
            }
        }
        float* rcat = ((RT & 1) ? bufB : bufA);
        {   // gl0 -> s_h[0..255], gr0 -> s_h[256..511] + d_gr0
            int o = tid >> 1, q2 = tid & 1;
            float gl = dot16(Wl + o * 64 + q2 * 32,      &rcat[q2 * 32])
                     + dot16(Wl + o * 64 + q2 * 32 + 16, &rcat[q2 * 32 + 16]);
            float gr = dot16(Wr + o * 64 + q2 * 32,      &rcat[q2 * 32])
                     + dot16(Wr + o * 64 + q2 * 32 + 16, &rcat[q2 * 32 + 16]);
            gl += __shfl_xor_sync(0xffffffffu, gl, 1);
            gr += __shfl_xor_sync(0xffffffffu, gr, 1);
            if (q2 == 0) { s_h[o] = gl; s_h[256 + o] = gr; d_gr0[o] = gr; }
        }
        __syncthreads();
        if (warp < 8) {                   // node-0 logits e0[h] (the exp reference)
            int h = warp >> 1, half = warp & 1, f = half * 32 + lane;
            float c = leaky(s_h[h * 64 + f] + s_h[256 + h * 64 + f]) * wattn[f];
            c = warpsum(c);
            if (lane == 0) s_e0[h * 2 + half] = c;
        }
        __syncthreads();
        if (tid < 4) {
            d_e0g[tid] = s_e0[tid * 2] + s_e0[tid * 2 + 1];
            atomicAdd(&d_zsum[tid], 1.f);           // node-0: exp(e0-e0)=1
        }
        if (tid < 256) atomicAdd(&d_paccsum[tid], s_h[256 + tid]);  // node-0 pacc
        __threadfence();
        __syncthreads();
        if (tid == 0) *(volatile int*)&d_flag1 = 1;   // release gr0 + e0
        // ---- wait for all node partials, then tiny combine ----
        if (tid == 0) {
            volatile int* c = &d_cnt1;
            while (*c < NODE_BLKS) __nanosleep(64);
            __threadfence();
        }
        __syncthreads();
        if (tid < 4) s_Zi[tid] = 1.f / d_zsum[tid];
        __syncthreads();
        if (tid < 64) {
            float h2 = 0.f;
            #pragma unroll
            for (int hh = 0; hh < 4; hh++)
                h2 += d_paccsum[hh * 64 + tid] * s_Zi[hh];
            s_h2[tid] = 0.25f * h2;
        }
        __syncthreads();
        {   // c0 from prefetched weights -> global broadcast
            float4 xa = *(const float4*)&s_h2[kb];
            float4 xb = *(const float4*)&s_h2[kb + 4];
            float p = d44(wc0a, xa) + d44(wc0b, xb);
            p = red8(p);
            if (q8 == 0) d_c0g[oid] = bd0v + p;
        }
        __threadfence();
        __syncthreads();
        if (tid == 0) {
            *(volatile int*)&d_go = 1;
            s_last = (atomicAdd(&d_cnt2, 1) == GRID - 1);
        }
        __syncthreads();
        if (s_last) {                     // cooperative end-of-launch reset
            if (tid < 256) d_paccsum[tid] = 0.f;
            if (tid < 4) d_zsum[tid] = 0.f;
            if (tid == 0) { d_cnt1 = 0; d_go = 0; d_flag1 = 0; __threadfence(); d_cnt2 = 0; }
        }
        return;
    }

    // ===================== node blocks 0..127 =====================
    {   // h rows (clamped pad): row-major AND k-pair packed [kp*20 + r*2 + parity]
        int r = tid >> 6, k = tid & 63;
        int ar_ = base + r; if (ar_ >= N_AMB) ar_ = N_AMB - 1;
        float hv = amb[ar_ * 64 + k];
        s_h[r * 64 + k] = hv;
        s_hk[(k >> 1) * 20 + r * 2 + (k & 1)] = hv;
    }
    __syncthreads();

    // -------- pass A: col-per-thread, k-pair packed f32x2 --------
    const int col = tid & 255;
    const int mat = tid >> 8;            // 0 = Wl (-> logits), 1 = Wr (-> pacc)
    const float* Wmat = mat ? Wr : Wl;
    float rowv[8];
    {
        unsigned long long acc[8];
        #pragma unroll
        for (int r = 0; r < 8; r++) acc[r] = 0ull;
        #pragma unroll
        for (int t = 0; t < 4; t++) {
            ulonglong2 wv0 = *(const ulonglong2*)(Wmat + col * 64 + t * 16);
            ulonglong2 wv1 = *(const ulonglong2*)(Wmat + col * 64 + t * 16 + 4);
            ulonglong2 wv2 = *(const ulonglong2*)(Wmat + col * 64 + t * 16 + 8);
            ulonglong2 wv3 = *(const ulonglong2*)(Wmat + col * 64 + t * 16 + 12);
            unsigned long long wp[8] = { wv0.x, wv0.y, wv1.x, wv1.y,
                                         wv2.x, wv2.y, wv3.x, wv3.y };
            #pragma unroll
            for (int j = 0; j < 8; j++) {
                int kp = t * 8 + j;
                const float* hb = &s_hk[kp * 20];
                ulonglong2 hA = *(const ulonglong2*)(hb);
                ulonglong2 hB = *(const ulonglong2*)(hb + 4);
                ulonglong2 hC = *(const ulonglong2*)(hb + 8);
                ulonglong2 hD = *(const ulonglong2*)(hb + 12);
                fma2(acc[0], wp[j], hA.x); fma2(acc[1], wp[j], hA.y);
                fma2(acc[2], wp[j], hB.x); fma2(acc[3], wp[j], hB.y);
                fma2(acc[4], wp[j], hC.x); fma2(acc[5], wp[j], hC.y);
                fma2(acc[6], wp[j], hD.x); fma2(acc[7], wp[j], hD.y);
            }
        }
        #pragma unroll
        for (int r = 0; r < 8; r++) rowv[r] = collapse(acc[r]);
    }
    // MLP stage-1 dots pre-barrier (overlaps cold Wd0 + flag wait)
    {
        const float4* w4 = (const float4*)(Wd0 + oid * 128 + kb);
        float4 a = w4[0], b = w4[1];
        #pragma unroll
        for (int r = 0; r < NPB; r++) {
            float4 xa = *(const float4*)&s_h[r * 64 + kb];
            float4 xb = *(const float4*)&s_h[r * 64 + kb + 4];
            float s = d44(a, xa) + d44(b, xb);
            s = red8(s);
            if (q8 == 0) s_p1[r * 64 + oid] = s;
        }
    }
    // prefetch MLP stage-2/3 weights into regs
    float4 w2a0, w2a1, w2b0, w2b1, w3a, w3b;
    float bb0, bb1, b3;
    const int r3 = tid >> 6, sub3 = tid & 63, o3 = sub3 >> 4, q16 = sub3 & 15;
    {
        const float4* w4 = (const float4*)(Wd1 + oid * 64 + kb);
        w2a0 = w4[0]; w2a1 = w4[1];
        const float4* w5 = (const float4*)(Wd1 + (64 + oid) * 64 + kb);
        w2b0 = w5[0]; w2b1 = w5[1];
        bb0 = bd1[oid]; bb1 = bd1[64 + oid];
        const float4* w6 = (const float4*)(Wd2 + o3 * 128 + q16 * 8);
        w3a = w6[0]; w3b = w6[1];
        b3 = bd2[o3];
    }
    if (tid == 0) {
        volatile int* f = &d_flag1;
        while (!*f) __nanosleep(32);
        __threadfence();
    }
    __syncthreads();
    if (tid < 4) s_e0s[tid] = d_e0g[tid];   // e0 reference -> smem

    // -------- pass B: logits from registers --------
    if (mat == 0) {
        float g0 = d_gr0[col];
        float wa = wattn[col & 63];
        #pragma unroll
        for (int r = 0; r < NPB; r++)
            s_v[col * 9 + r] = leaky(rowv[r] + g0) * wa;
    }
    __syncthreads();
    {   // reduce v over 64 cols per (head,row): 16 threads each
        int hr = tid >> 4, sub = tid & 15;
        int h = hr >> 3, r = hr & 7;
        int cb = h * 64 + sub * 4;
        float s = s_v[cb * 9 + r] + s_v[(cb + 1) * 9 + r]
                + s_v[(cb + 2) * 9 + r] + s_v[(cb + 3) * 9 + r];
        s += __shfl_xor_sync(0xffffffffu, s, 1);
        s += __shfl_xor_sync(0xffffffffu, s, 2);
        s += __shfl_xor_sync(0xffffffffu, s, 4);
        s += __shfl_xor_sync(0xffffffffu, s, 8);
        if (sub == 0) s_eall[h * 8 + r] = s;
    }
    __syncthreads();
    if (tid < 32) {                     // w = exp(e - e0); z via 8-lane shfl -> atomic
        int h = tid >> 3, r = tid & 7;
        float w = (base + r < N_AMB) ? __expf(s_eall[tid] - s_e0s[h]) : 0.f;
        s_wv[tid] = w;
        float z = w;
        z += __shfl_xor_sync(0xffffffffu, z, 1);
        z += __shfl_xor_sync(0xffffffffu, z, 2);
        z += __shfl_xor_sync(0xffffffffu, z, 4);
        if (r == 0) atomicAdd(&d_zsum[h], z);
    }
    __syncthreads();
    if (mat == 1) {                      // pacc accumulated via RED (no combine gather)
        int h = col >> 6;
        float accf = 0.f;
        #pragma unroll
        for (int r = 0; r < NPB; r++)
            accf = fmaf(s_wv[h * 8 + r], rowv[r], accf);
        atomicAdd(&d_paccsum[col], accf);
    }
    __threadfence();
    __syncthreads();
    if (tid == 0) {
        atomicAdd(&d_cnt1, 1);
        volatile int* g = &d_go;         // combiner releases
        while (!*g) __nanosleep(64);
        __threadfence();
    }
    __syncthreads();

    // read broadcast c0
    if (tid < 64) s_c0[tid] = d_c0g[tid];
    __syncthreads();

    // -------- MLP finish --------
    s_y0[tid] = leaky(s_c0[tid & 63] + s_p1[tid]);   // stage 1 elementwise
    __syncthreads();
    #pragma unroll
    for (int r = 0; r < NPB; r++) {      // stage 2
        float4 xa = *(const float4*)&s_y0[r * 64 + kb];
        float4 xb = *(const float4*)&s_y0[r * 64 + kb + 4];
        float s0 = d44(w2a0, xa) + d44(w2a1, xb);
        float s1 = d44(w2b0, xa) + d44(w2b1, xb);
        s0 = red8(s0);
        s1 = red8(s1);
        if (q8 == 0) {
            s_y1[r * 128 + oid]      = leaky(bb0 + s0);
            s_y1[r * 128 + 64 + oid] = leaky(bb1 + s1);
        }
    }
    __syncthreads();
    {                                    // stage 3 + sigmoid
        float4 ya = *(const float4*)&s_y1[r3 * 128 + q16 * 8];
        float4 yb = *(const float4*)&s_y1[r3 * 128 + q16 * 8 + 4];
        float p = d44(w3a, ya) + d44(w3b, yb);
        p += __shfl_xor_sync(0xffffffffu, p, 1);
        p += __shfl_xor_sync(0xffffffffu, p, 2);
        p += __shfl_xor_sync(0xffffffffu, p, 4);
        p += __shfl_xor_sync(0xffffffffu, p, 8);
        int arr = base + r3;
        if (q16 == 0 && arr < N_AMB)
            out[arr * 4 + o3] = 1.f / (1.f + __expf(-(b3 + p)));
    }

    if (tid == 0) s_last = (atomicAdd(&d_cnt2, 1) == GRID - 1);
    __syncthreads();
    if (s_last) {                        // cooperative end-of-launch reset
        if (tid < 256) d_paccsum[tid] = 0.f;
        if (tid < 4) d_zsum[tid] = 0.f;
        if (tid == 0) { d_cnt1 = 0; d_go = 0; d_flag1 = 0; __threadfence(); d_cnt2 = 0; }
    }
}

extern "C" void kernel_launch(void* const* d_in, const int* in_sizes, int n_in,
                              void* d_out, int out_size) {
    const float* hidden = (const float*)d_in[0];
    const float* amb    = (const float*)d_in[1];
    const float* ta     = (const float*)d_in[2];
    const float* Wself  = (const float*)d_in[3];
    const float* bself  = (const float*)d_in[4];
    const float* Wmerge = (const float*)d_in[5];
    const float* bmerge = (const float*)d_in[6];
    const float* Wtrans = (const float*)d_in[7];
    const float* btrans = (const float*)d_in[8];
    const float* Wl     = (const float*)d_in[9];
    const float* Wr     = (const float*)d_in[10];
    const float* wattn  = (const float*)d_in[11];
    const float* Wd0    = (const float*)d_in[12];
    const float* bd0    = (const float*)d_in[13];
    const float* Wd1    = (const float*)d_in[14];
    const float* bd1    = (const float*)d_in[15];
    const float* Wd2    = (const float*)d_in[16];
    const float* bd2    = (const float*)d_in[17];
    float* out = (float*)d_out;

    mega<<<GRID, NT>>>(hidden, amb, ta, Wself, bself, Wmerge, bmerge,
                       Wtrans, btrans, Wl, Wr, wattn,
                       Wd0, bd0, Wd1, bd1, Wd2, bd2, out);
}

// round 15
// speedup vs baseline: 1.1437x; 1.0910x over previous
#include <cuda_runtime.h>
#include <math.h>

#define RT 4
#define N_AMB 1023
#define SLOPE 0.2f
#define NPB 8
#define NODE_BLKS 128
#define GRID 129
#define NT 512

__device__ float d_gr0[256];
__device__ float d_e0g[4];
__device__ float d_paccsum[256];   // atomic-accumulated; zeroed by last block each launch
__device__ float d_zsum[4];        // atomic-accumulated; zeroed by last block each launch
__device__ int   d_flag1, d_cnt1, d_cnt2;

__device__ __forceinline__ float leaky(float x) { return x >= 0.f ? x : SLOPE * x; }
__device__ __forceinline__ float red8(float v) {
    v += __shfl_xor_sync(0xffffffffu, v, 1);
    v += __shfl_xor_sync(0xffffffffu, v, 2);
    v += __shfl_xor_sync(0xffffffffu, v, 4);
    return v;
}
__device__ __forceinline__ float warpsum(float v) {
    #pragma unroll
    for (int off = 16; off; off >>= 1) v += __shfl_xor_sync(0xffffffffu, v, off);
    return v;
}
__device__ __forceinline__ float dot16(const float* __restrict__ w, const float* __restrict__ x) {
    const float4* w4 = (const float4*)w;
    float4 a = w4[0], b = w4[1], c = w4[2], d = w4[3];
    return a.x*x[0] + a.y*x[1] + a.z*x[2] + a.w*x[3]
         + b.x*x[4] + b.y*x[5] + b.z*x[6] + b.w*x[7]
         + c.x*x[8] + c.y*x[9] + c.z*x[10] + c.w*x[11]
         + d.x*x[12] + d.y*x[13] + d.z*x[14] + d.w*x[15];
}
__device__ __forceinline__ float d44(float4 w, float4 x) {
    return w.x*x.x + w.y*x.y + w.z*x.z + w.w*x.w;
}
__device__ __forceinline__ void unpack2(unsigned long long v, float& x, float& y) {
    asm("mov.b64 {%0, %1}, %2;" : "=f"(x), "=f"(y) : "l"(v));
}
__device__ __forceinline__ void fma2(unsigned long long& d, unsigned long long a, unsigned long long b) {
    asm("fma.rn.f32x2 %0, %1, %2, %0;" : "+l"(d) : "l"(a), "l"(b));
}
__device__ __forceinline__ float collapse(unsigned long long v) {
    float x, y; unpack2(v, x, y); return x + y;
}

__global__ void __launch_bounds__(NT, 1)
mega(const float* __restrict__ hidden, const float* __restrict__ amb,
     const float* __restrict__ ta,
     const float* __restrict__ Wself,  const float* __restrict__ bself,
     const float* __restrict__ Wmerge, const float* __restrict__ bmerge,
     const float* __restrict__ Wtrans, const float* __restrict__ btrans,
     const float* __restrict__ Wl,     const float* __restrict__ Wr,
     const float* __restrict__ wattn,
     const float* __restrict__ Wd0,    const float* __restrict__ bd0,
     const float* __restrict__ Wd1,    const float* __restrict__ bd1,
     const float* __restrict__ Wd2,    const float* __restrict__ bd2,
     float* __restrict__ out) {
    __shared__ __align__(16) float pool[8192];
    __shared__ __align__(16) float s_hk[640];   // h k-pair-packed; routing: rtmp|bufA|bufB
    __shared__ __align__(16) float s_h[512];    // h row-major; routing: rin|ravg then gl|gr
    __shared__ float s_eall[32], s_wv[32];
    __shared__ float s_Zi[4], s_h2[64], s_c0[64], s_e0[8], s_e0s[4];
    __shared__ int s_last;

    float* const s_v  = pool;            // 256 cols x pad9
    float* const s_p1 = pool + 2304;
    float* const s_y0 = pool + 2816;
    float* const s_y1 = pool + 3328;

    const int tid = threadIdx.x, lane = tid & 31, warp = tid >> 5;
    const int oid = tid >> 3, q8 = tid & 7;
    const int blk = blockIdx.x;
    const int base = blk * NPB;
    const int kb = q8 * 8;

    // ================= block 128: routing + node 0 (no combiner role) ========
    if (blk == NODE_BLKS) {
        float* rin  = s_h;            // 64
        float* ravg = s_h + 64;       // 256
        float* rtmp = s_hk;           // 256
        float* bufA = s_hk + 256;     // 128
        float* bufB = s_hk + 384;     // 128
        if (tid >= 256) {             // prefetch Wmerge 32KB into pool
            int t = tid - 256;
            float4* dst = (float4*)pool;
            const float4* src = (const float4*)Wmerge;
            #pragma unroll
            for (int i = 0; i < 8; i++) dst[t + i * 256] = src[t + i * 256];
        } else {
            if (tid < 64) rin[tid] = hidden[tid];
            int rt = tid >> 6, oo = tid & 63;
            ravg[tid] = (ta[(rt * 3 + 0) * 64 + oo] + ta[(rt * 3 + 1) * 64 + oo] +
                         ta[(rt * 3 + 2) * 64 + oo]) * (1.f / 3.f);
        }
        __syncthreads();
        if (tid < 256) {
            int o4 = tid >> 2, q4 = tid & 3;
            float s = dot16(Wself + o4 * 64 + q4 * 16, &rin[q4 * 16]);
            s += __shfl_xor_sync(0xffffffffu, s, 1);
            s += __shfl_xor_sync(0xffffffffu, s, 2);
            if (q4 == 0) bufA[o4] = bself[o4] + s;
            int rt = tid >> 6, oo = tid & 63;
            const float* av = &ravg[rt * 64];
            float t = btrans[rt * 64 + oo];
            t += dot16(Wtrans + rt * 4096 + oo * 64,      av);
            t += dot16(Wtrans + rt * 4096 + oo * 64 + 16, av + 16);
            t += dot16(Wtrans + rt * 4096 + oo * 64 + 32, av + 32);
            t += dot16(Wtrans + rt * 4096 + oo * 64 + 48, av + 48);
            rtmp[tid] = t;
        }
        __syncthreads();
        if (tid < 64) bufA[64 + tid] = rtmp[tid];
        __syncthreads();
        {   // double-buffered merge chain: 1 sync per iteration
            float bm = bmerge[oid];
            float* bufs[2] = { bufA, bufB };
            #pragma unroll
            for (int rt = 0; rt < RT; rt++) {
                float* cur = bufs[rt & 1];
                float* nxt = bufs[(rt + 1) & 1];
                float m = dot16(&pool[oid * 128 + q8 * 16], &cur[q8 * 16]);
                m = red8(m);
                if (q8 == 0) nxt[oid] = leaky(bm + m);
                if (tid < 64 && rt < 3) nxt[64 + tid] = rtmp[(rt + 1) * 64 + tid];
                __syncthreads();
            }
        }
        float* rcat = ((RT & 1) ? bufB : bufA);
        {   // gl0 -> s_h[0..255], gr0 -> s_h[256..511] + d_gr0
            int o = tid >> 1, q2 = tid & 1;
            float gl = dot16(Wl + o * 64 + q2 * 32,      &rcat[q2 * 32])
                     + dot16(Wl + o * 64 + q2 * 32 + 16, &rcat[q2 * 32 + 16]);
            float gr = dot16(Wr + o * 64 + q2 * 32,      &rcat[q2 * 32])
                     + dot16(Wr + o * 64 + q2 * 32 + 16, &rcat[q2 * 32 + 16]);
            gl += __shfl_xor_sync(0xffffffffu, gl, 1);
            gr += __shfl_xor_sync(0xffffffffu, gr, 1);
            if (q2 == 0) { s_h[o] = gl; s_h[256 + o] = gr; d_gr0[o] = gr; }
        }
        __syncthreads();
        if (warp < 8) {                   // node-0 logits e0[h] (the exp reference)
            int h = warp >> 1, half = warp & 1, f = half * 32 + lane;
            float c = leaky(s_h[h * 64 + f] + s_h[256 + h * 64 + f]) * wattn[f];
            c = warpsum(c);
            if (lane == 0) s_e0[h * 2 + half] = c;
        }
        __syncthreads();
        if (tid < 4) {
            d_e0g[tid] = s_e0[tid * 2] + s_e0[tid * 2 + 1];
            atomicAdd(&d_zsum[tid], 1.f);           // node-0: exp(e0-e0)=1
        }
        if (tid < 256) atomicAdd(&d_paccsum[tid], s_h[256 + tid]);  // node-0 pacc
        __threadfence();
        __syncthreads();
        if (tid == 0) {
            *(volatile int*)&d_flag1 = 1;           // release gr0 + e0
            atomicAdd(&d_cnt1, 1);                  // node-0 partials published
            s_last = (atomicAdd(&d_cnt2, 1) == GRID - 1);
        }
        __syncthreads();
        if (s_last) {                     // cooperative end-of-launch reset
            if (tid < 256) d_paccsum[tid] = 0.f;
            if (tid < 4) d_zsum[tid] = 0.f;
            if (tid == 0) { d_cnt1 = 0; d_flag1 = 0; __threadfence(); d_cnt2 = 0; }
        }
        return;
    }

    // ===================== node blocks 0..127 =====================
    {   // h rows (clamped pad): row-major AND k-pair packed [kp*20 + r*2 + parity]
        int r = tid >> 6, k = tid & 63;
        int ar_ = base + r; if (ar_ >= N_AMB) ar_ = N_AMB - 1;
        float hv = amb[ar_ * 64 + k];
        s_h[r * 64 + k] = hv;
        s_hk[(k >> 1) * 20 + r * 2 + (k & 1)] = hv;
    }
    __syncthreads();

    // -------- pass A: col-per-thread, k-pair packed f32x2 --------
    const int col = tid & 255;
    const int mat = tid >> 8;            // 0 = Wl (-> logits), 1 = Wr (-> pacc)
    const float* Wmat = mat ? Wr : Wl;
    float rowv[8];
    {
        unsigned long long acc[8];
        #pragma unroll
        for (int r = 0; r < 8; r++) acc[r] = 0ull;
        #pragma unroll
        for (int t = 0; t < 4; t++) {
            ulonglong2 wv0 = *(const ulonglong2*)(Wmat + col * 64 + t * 16);
            ulonglong2 wv1 = *(const ulonglong2*)(Wmat + col * 64 + t * 16 + 4);
            ulonglong2 wv2 = *(const ulonglong2*)(Wmat + col * 64 + t * 16 + 8);
            ulonglong2 wv3 = *(const ulonglong2*)(Wmat + col * 64 + t * 16 + 12);
            unsigned long long wp[8] = { wv0.x, wv0.y, wv1.x, wv1.y,
                                         wv2.x, wv2.y, wv3.x, wv3.y };
            #pragma unroll
            for (int j = 0; j < 8; j++) {
                int kp = t * 8 + j;
                const float* hb = &s_hk[kp * 20];
                ulonglong2 hA = *(const ulonglong2*)(hb);
                ulonglong2 hB = *(const ulonglong2*)(hb + 4);
                ulonglong2 hC = *(const ulonglong2*)(hb + 8);
                ulonglong2 hD = *(const ulonglong2*)(hb + 12);
                fma2(acc[0], wp[j], hA.x); fma2(acc[1], wp[j], hA.y);
                fma2(acc[2], wp[j], hB.x); fma2(acc[3], wp[j], hB.y);
                fma2(acc[4], wp[j], hC.x); fma2(acc[5], wp[j], hC.y);
                fma2(acc[6], wp[j], hD.x); fma2(acc[7], wp[j], hD.y);
            }
        }
        #pragma unroll
        for (int r = 0; r < 8; r++) rowv[r] = collapse(acc[r]);
    }
    // MLP stage-1 dots pre-barrier (overlaps cold Wd0 + flag wait)
    {
        const float4* w4 = (const float4*)(Wd0 + oid * 128 + kb);
        float4 a = w4[0], b = w4[1];
        #pragma unroll
        for (int r = 0; r < NPB; r++) {
            float4 xa = *(const float4*)&s_h[r * 64 + kb];
            float4 xb = *(const float4*)&s_h[r * 64 + kb + 4];
            float s = d44(a, xa) + d44(b, xb);
            s = red8(s);
            if (q8 == 0) s_p1[r * 64 + oid] = s;
        }
    }
    // prefetch MLP stage-2/3 + c0 weights into regs (cold DRAM; off critical tail)
    float4 w2a0, w2a1, w2b0, w2b1, w3a, w3b, wc0a, wc0b;
    float bb0, bb1, b3, bd0v;
    const int r3 = tid >> 6, sub3 = tid & 63, o3 = sub3 >> 4, q16 = sub3 & 15;
    {
        const float4* w4 = (const float4*)(Wd1 + oid * 64 + kb);
        w2a0 = w4[0]; w2a1 = w4[1];
        const float4* w5 = (const float4*)(Wd1 + (64 + oid) * 64 + kb);
        w2b0 = w5[0]; w2b1 = w5[1];
        bb0 = bd1[oid]; bb1 = bd1[64 + oid];
        const float4* w6 = (const float4*)(Wd2 + o3 * 128 + q16 * 8);
        w3a = w6[0]; w3b = w6[1];
        b3 = bd2[o3];
        wc0a = *(const float4*)(Wd0 + oid * 128 + 64 + kb);
        wc0b = *(const float4*)(Wd0 + oid * 128 + 64 + kb + 4);
        bd0v = bd0[oid];
    }
    if (tid == 0) {
        volatile int* f = &d_flag1;
        while (!*f) __nanosleep(32);
        __threadfence();
    }
    __syncthreads();
    if (tid < 4) s_e0s[tid] = d_e0g[tid];   // e0 reference -> smem

    // -------- pass B: logits from registers --------
    if (mat == 0) {
        float g0 = d_gr0[col];
        float wa = wattn[col & 63];
        #pragma unroll
        for (int r = 0; r < NPB; r++)
            s_v[col * 9 + r] = leaky(rowv[r] + g0) * wa;
    }
    __syncthreads();
    {   // reduce v over 64 cols per (head,row): 16 threads each
        int hr = tid >> 4, sub = tid & 15;
        int h = hr >> 3, r = hr & 7;
        int cb = h * 64 + sub * 4;
        float s = s_v[cb * 9 + r] + s_v[(cb + 1) * 9 + r]
                + s_v[(cb + 2) * 9 + r] + s_v[(cb + 3) * 9 + r];
        s += __shfl_xor_sync(0xffffffffu, s, 1);
        s += __shfl_xor_sync(0xffffffffu, s, 2);
        s += __shfl_xor_sync(0xffffffffu, s, 4);
        s += __shfl_xor_sync(0xffffffffu, s, 8);
        if (sub == 0) s_eall[h * 8 + r] = s;
    }
    __syncthreads();
    if (tid < 32) {                     // w = exp(e - e0); z via 8-lane shfl -> atomic
        int h = tid >> 3, r = tid & 7;
        float w = (base + r < N_AMB) ? __expf(s_eall[tid] - s_e0s[h]) : 0.f;
        s_wv[tid] = w;
        float z = w;
        z += __shfl_xor_sync(0xffffffffu, z, 1);
        z += __shfl_xor_sync(0xffffffffu, z, 2);
        z += __shfl_xor_sync(0xffffffffu, z, 4);
        if (r == 0) atomicAdd(&d_zsum[h], z);
    }
    __syncthreads();
    if (mat == 1) {                      // pacc accumulated via RED (no combine gather)
        int h = col >> 6;
        float accf = 0.f;
        #pragma unroll
        for (int r = 0; r < NPB; r++)
            accf = fmaf(s_wv[h * 8 + r], rowv[r], accf);
        atomicAdd(&d_paccsum[col], accf);
    }
    __threadfence();
    __syncthreads();
    if (tid == 0) {
        atomicAdd(&d_cnt1, 1);
        volatile int* c = &d_cnt1;       // wait until ALL 129 blocks published
        while (*c < GRID) __nanosleep(32);
        __threadfence();
    }
    __syncthreads();

    // -------- decentralized combine: h2 + c0 computed locally --------
    if (tid < 4) s_Zi[tid] = 1.f / d_zsum[tid];
    __syncthreads();
    if (tid < 64) {
        float h2 = 0.f;
        #pragma unroll
        for (int hh = 0; hh < 4; hh++)
            h2 += d_paccsum[hh * 64 + tid] * s_Zi[hh];
        s_h2[tid] = 0.25f * h2;
    }
    __syncthreads();
    {   // c0 from prefetched weights
        float4 xa = *(const float4*)&s_h2[kb];
        float4 xb = *(const float4*)&s_h2[kb + 4];
        float p = d44(wc0a, xa) + d44(wc0b, xb);
        p = red8(p);
        if (q8 == 0) s_c0[oid] = bd0v + p;
    }
    __syncthreads();

    // -------- MLP finish --------
    s_y0[tid] = leaky(s_c0[tid & 63] + s_p1[tid]);   // stage 1 elementwise
    __syncthreads();
    #pragma unroll
    for (int r = 0; r < NPB; r++) {      // stage 2
        float4 xa = *(const float4*)&s_y0[r * 64 + kb];
        float4 xb = *(const float4*)&s_y0[r * 64 + kb + 4];
        float s0 = d44(w2a0, xa) + d44(w2a1, xb);
        float s1 = d44(w2b0, xa) + d44(w2b1, xb);
        s0 = red8(s0);
        s1 = red8(s1);
        if (q8 == 0) {
            s_y1[r * 128 + oid]      = leaky(bb0 + s0);
            s_y1[r * 128 + 64 + oid] = leaky(bb1 + s1);
        }
    }
    __syncthreads();
    {                                    // stage 3 + sigmoid
        float4 ya = *(const float4*)&s_y1[r3 * 128 + q16 * 8];
        float4 yb = *(const float4*)&s_y1[r3 * 128 + q16 * 8 + 4];
        float p = d44(w3a, ya) + d44(w3b, yb);
        p += __shfl_xor_sync(0xffffffffu, p, 1);
        p += __shfl_xor_sync(0xffffffffu, p, 2);
        p += __shfl_xor_sync(0xffffffffu, p, 4);
        p += __shfl_xor_sync(0xffffffffu, p, 8);
        int arr = base + r3;
        if (q16 == 0 && arr < N_AMB)
            out[arr * 4 + o3] = 1.f / (1.f + __expf(-(b3 + p)));
    }

    if (tid == 0) s_last = (atomicAdd(&d_cnt2, 1) == GRID - 1);
    __syncthreads();
    if (s_last) {                        // cooperative end-of-launch reset
        if (tid < 256) d_paccsum[tid] = 0.f;
        if (tid < 4) d_zsum[tid] = 0.f;
        if (tid == 0) { d_cnt1 = 0; d_flag1 = 0; __threadfence(); d_cnt2 = 0; }
    }
}

extern "C" void kernel_launch(void* const* d_in, const int* in_sizes, int n_in,
                              void* d_out, int out_size) {
    const float* hidden = (const float*)d_in[0];
    const float* amb    = (const float*)d_in[1];
    const float* ta     = (const float*)d_in[2];
    const float* Wself  = (const float*)d_in[3];
    const float* bself  = (const float*)d_in[4];
    const float* Wmerge = (const float*)d_in[5];
    const float* bmerge = (const float*)d_in[6];
    const float* Wtrans = (const float*)d_in[7];
    const float* btrans = (const float*)d_in[8];
    const float* Wl     = (const float*)d_in[9];
    const float* Wr     = (const float*)d_in[10];
    const float* wattn  = (const float*)d_in[11];
    const float* Wd0    = (const float*)d_in[12];
    const float* bd0    = (const float*)d_in[13];
    const float* Wd1    = (const float*)d_in[14];
    const float* bd1    = (const float*)d_in[15];
    const float* Wd2    = (const float*)d_in[16];
    const float* bd2    = (const float*)d_in[17];
    float* out = (float*)d_out;

    mega<<<GRID, NT>>>(hidden, amb, ta, Wself, bself, Wmerge, bmerge,
                       Wtrans, btrans, Wl, Wr, wattn,
                       Wd0, bd0, Wd1, bd1, Wd2, bd2, out);
}